// round 1
// baseline (speedup 1.0000x reference)
#include <cuda_runtime.h>
#include <math.h>

#define NANCH 49104
#define NCLS  90
#define NBATCH 8
#define NTASK (NBATCH * NCLS)   // 720
#define KPRE  5000
#define KPOST 100

// ---------------- scratch (device globals: no allocation allowed) ----------------
__device__ unsigned g_keysT[(size_t)NTASK * NANCH];      // transposed order-preserving keys
__device__ float4   g_cand_boxes[NTASK * KPRE];
__device__ float    g_cand_scores[NTASK * KPRE];
__device__ float4   g_nms_boxes[NTASK * KPOST];
__device__ float    g_nms_scores[NTASK * KPOST];

__constant__ int c_lvl_off[6]    = {0, 36864, 46080, 48384, 48960, 49104};
__constant__ int c_lvl_feat[5]   = {64, 32, 16, 8, 4};
__constant__ int c_lvl_stride[5] = {8, 16, 32, 64, 128};

__device__ __forceinline__ unsigned f2key(float f) {
    unsigned u = __float_as_uint(f);
    return (u & 0x80000000u) ? ~u : (u | 0x80000000u);
}
__device__ __forceinline__ float key2f(unsigned k) {
    unsigned u = (k & 0x80000000u) ? (k ^ 0x80000000u) : ~k;
    return __uint_as_float(u);
}

// ---------------- kernel 1: transpose logits -> keys [B,C,N] ----------------
__global__ void k_transpose(const float* __restrict__ logits) {
    __shared__ unsigned tile[32][33];
    int b  = blockIdx.z;
    int n0 = blockIdx.x * 32, c0 = blockIdx.y * 32;
    #pragma unroll
    for (int j = 0; j < 4; ++j) {
        int ty = threadIdx.y + j * 8;
        int n = n0 + ty, c = c0 + threadIdx.x;
        if (n < NANCH && c < NCLS)
            tile[ty][threadIdx.x] = f2key(logits[((size_t)b * NANCH + n) * NCLS + c]);
    }
    __syncthreads();
    #pragma unroll
    for (int j = 0; j < 4; ++j) {
        int ty = threadIdx.y + j * 8;
        int c = c0 + ty, n = n0 + threadIdx.x;
        if (n < NANCH && c < NCLS)
            g_keysT[((size_t)b * NCLS + c) * NANCH + n] = tile[threadIdx.x][ty];
    }
}

// ---------------- decode one candidate & write to scratch ----------------
__device__ void decode_write(int task, int slot, int n, unsigned key,
                             const float4* __restrict__ deltas, int b) {
    int l = 0;
    #pragma unroll
    for (int q = 1; q < 5; ++q) if (n >= c_lvl_off[q]) l = q;
    int j    = n - c_lvl_off[l];
    int cell = j / 9, a = j - cell * 9;
    int feat = c_lvl_feat[l];
    int row  = cell / feat, col = cell - row * feat;
    int stride = c_lvl_stride[l];
    int iscale = a / 3, ri = a - iscale * 3;

    double rr   = (ri == 0) ? 1.0 : (ri == 1 ? 0.5 : 2.0);
    double base = exp2((double)iscale / 3.0) * (double)stride * 4.0;
    double sq   = sqrt(rr);
    float hh = (float)(base / sq / 2.0);
    float hw = (float)(base * sq / 2.0);

    float cy = ((float)row + 0.5f) * (float)stride;
    float cx = ((float)col + 0.5f) * (float)stride;
    float ay1 = __fsub_rn(cy, hh), ay2 = __fadd_rn(cy, hh);
    float ax1 = __fsub_rn(cx, hw), ax2 = __fadd_rn(cx, hw);
    float ah  = __fsub_rn(ay2, ay1), aw = __fsub_rn(ax2, ax1);
    float acy = __fmul_rn(__fadd_rn(ay1, ay2), 0.5f);
    float acx = __fmul_rn(__fadd_rn(ax1, ax2), 0.5f);

    float4 d = deltas[(size_t)b * NANCH + n];
    float ncy = __fadd_rn(__fmul_rn(d.x, ah), acy);
    float ncx = __fadd_rn(__fmul_rn(d.y, aw), acx);
    float h   = __fmul_rn(expf(d.z), ah);
    float w   = __fmul_rn(expf(d.w), aw);

    const float inv = 1.0f / 512.0f;
    float y1 = __fsub_rn(ncy, __fmul_rn(h, 0.5f)) * inv;
    float x1 = __fsub_rn(ncx, __fmul_rn(w, 0.5f)) * inv;
    float y2 = __fadd_rn(ncy, __fmul_rn(h, 0.5f)) * inv;
    float x2 = __fadd_rn(ncx, __fmul_rn(w, 0.5f)) * inv;
    y1 = fminf(fmaxf(y1, 0.0f), 1.0f);
    x1 = fminf(fmaxf(x1, 0.0f), 1.0f);
    y2 = fminf(fmaxf(y2, 0.0f), 1.0f);
    x2 = fminf(fmaxf(x2, 0.0f), 1.0f);

    float logit = key2f(key);
    float sc = __fdiv_rn(1.0f, __fadd_rn(1.0f, expf(-logit)));
    g_cand_scores[(size_t)task * KPRE + slot] = sc;
    g_cand_boxes [(size_t)task * KPRE + slot] = make_float4(y1, x1, y2, x2);
}

// ---------------- kernel 2: exact top-5000 select (radix) + decode ----------------
extern __shared__ unsigned smA[];
__global__ void __launch_bounds__(512) k_select(const float4* __restrict__ deltas) {
    unsigned* keys = smA;              // [NANCH]
    unsigned* hist = smA + NANCH;      // [2048]
    __shared__ unsigned partial[512];
    __shared__ int bc_v, bc_k;
    __shared__ int cntG, cntT;

    int tid  = threadIdx.x;
    int task = blockIdx.x;
    int b    = task / NCLS;

    const unsigned* kt = g_keysT + (size_t)task * NANCH;
    for (int i = tid; i < NANCH; i += 512) keys[i] = kt[i];
    __syncthreads();

    unsigned prefix = 0;
    int Krem = KPRE;
    const int SH[3] = {21, 10, 0};
    const int BT[3] = {11, 11, 10};

    for (int pass = 0; pass < 3; ++pass) {
        int shift = SH[pass], bits = BT[pass], nb = 1 << bits;
        for (int i = tid; i < nb; i += 512) hist[i] = 0;
        __syncthreads();
        int top = shift + bits;
        for (int i = tid; i < NANCH; i += 512) {
            unsigned k = keys[i];
            if (pass == 0 || (k >> top) == prefix)
                atomicAdd(&hist[(k >> shift) & (unsigned)(nb - 1)], 1u);
        }
        __syncthreads();
        int cs = nb >> 9;                 // bins per thread (4 or 2)
        int base0 = tid * cs;
        unsigned ssum = 0;
        for (int j2 = 0; j2 < cs; ++j2) ssum += hist[base0 + j2];
        partial[tid] = ssum;
        __syncthreads();
        // inclusive suffix scan (Hillis-Steele)
        for (int off = 1; off < 512; off <<= 1) {
            unsigned add = (tid + off < 512) ? partial[tid + off] : 0u;
            __syncthreads();
            partial[tid] += add;
            __syncthreads();
        }
        unsigned St  = partial[tid];
        unsigned Stn = (tid < 511) ? partial[tid + 1] : 0u;
        if (St >= (unsigned)Krem && Stn < (unsigned)Krem) {
            unsigned acc = Stn;
            for (int j2 = cs - 1; j2 >= 0; --j2) {
                unsigned hv = hist[base0 + j2];
                acc += hv;
                if (acc >= (unsigned)Krem) {
                    bc_v = base0 + j2;
                    bc_k = Krem - (int)(acc - hv);
                    break;
                }
            }
        }
        __syncthreads();
        prefix = (prefix << bits) | (unsigned)bc_v;
        Krem   = bc_k;
        __syncthreads();
    }
    unsigned Tkey = prefix;            // exact 5000th-largest key
    int needT = Krem;                  // ties of Tkey to include

    if (tid == 0) { cntG = 0; cntT = 0; }
    __syncthreads();
    for (int i = tid; i < NANCH; i += 512) {
        unsigned k = keys[i];
        if (k > Tkey) {
            int slot = atomicAdd(&cntG, 1);
            decode_write(task, slot, i, k, deltas, b);
        }
    }
    __syncthreads();
    int G = cntG;
    for (int i = tid; i < NANCH; i += 512) {
        unsigned k = keys[i];
        if (k == Tkey) {
            int t = atomicAdd(&cntT, 1);
            if (t < needT) decode_write(task, G + t, i, k, deltas, b);
        }
    }
}

// ---------------- kernel 3: greedy NMS (100 picks) per task ----------------
extern __shared__ unsigned char smB[];
__global__ void __launch_bounds__(512) k_nms() {
    float4* bx = (float4*)smB;                 // [KPRE]
    float*  s  = (float*)(smB + KPRE * 16);    // [KPRE]
    __shared__ float wv[16]; __shared__ int wi[16];
    __shared__ float rv_s;   __shared__ int ri_s;

    int tid = threadIdx.x, task = blockIdx.x;
    const float*  cs = g_cand_scores + (size_t)task * KPRE;
    const float4* cb = g_cand_boxes  + (size_t)task * KPRE;
    for (int i = tid; i < KPRE; i += 512) { s[i] = cs[i]; bx[i] = cb[i]; }
    __syncthreads();

    for (int p = 0; p < KPOST; ++p) {
        // ---- stable block argmax ----
        float v = -1e30f; int idx = 0;
        for (int i = tid; i < KPRE; i += 512) {
            float sv = s[i];
            if (sv > v) { v = sv; idx = i; }
        }
        #pragma unroll
        for (int o = 16; o; o >>= 1) {
            float ov = __shfl_down_sync(0xffffffffu, v, o);
            int   oi = __shfl_down_sync(0xffffffffu, idx, o);
            if (ov > v || (ov == v && oi < idx)) { v = ov; idx = oi; }
        }
        if ((tid & 31) == 0) { wv[tid >> 5] = v; wi[tid >> 5] = idx; }
        __syncthreads();
        if (tid < 32) {
            float v2 = (tid < 16) ? wv[tid] : -1e30f;
            int   i2 = (tid < 16) ? wi[tid] : 0;
            #pragma unroll
            for (int o = 8; o; o >>= 1) {
                float ov = __shfl_down_sync(0xffffffffu, v2, o);
                int   oi = __shfl_down_sync(0xffffffffu, i2, o);
                if (ov > v2 || (ov == v2 && oi < i2)) { v2 = ov; i2 = oi; }
            }
            if (tid == 0) { rv_s = v2; ri_s = i2; }
        }
        __syncthreads();
        float rv = rv_s; int ri = ri_s;

        if (rv <= 0.2f) {   // all remaining picks are invalid -> zeros
            for (int q = p + tid; q < KPOST; q += 512) {
                g_nms_scores[(size_t)task * KPOST + q] = 0.0f;
                g_nms_boxes [(size_t)task * KPOST + q] = make_float4(0.f, 0.f, 0.f, 0.f);
            }
            break;
        }
        float4 bb = bx[ri];
        if (tid == 0) {
            g_nms_scores[(size_t)task * KPOST + p] = rv;
            g_nms_boxes [(size_t)task * KPOST + p] = bb;
        }
        // ---- suppression (matches reference: only IoU > 0.5 kills) ----
        float a1 = __fmul_rn(__fsub_rn(bb.z, bb.x), __fsub_rn(bb.w, bb.y));
        for (int i = tid; i < KPRE; i += 512) {
            float4 o4 = bx[i];
            float yy1 = fmaxf(bb.x, o4.x), xx1 = fmaxf(bb.y, o4.y);
            float yy2 = fminf(bb.z, o4.z), xx2 = fminf(bb.w, o4.w);
            float ih = fmaxf(__fsub_rn(yy2, yy1), 0.0f);
            float iw = fmaxf(__fsub_rn(xx2, xx1), 0.0f);
            float inter = __fmul_rn(ih, iw);
            float a2 = __fmul_rn(__fsub_rn(o4.z, o4.x), __fsub_rn(o4.w, o4.y));
            float den = __fadd_rn(__fsub_rn(__fadd_rn(a1, a2), inter), 1e-8f);
            float iou = __fdiv_rn(inter, den);
            if (iou > 0.5f) s[i] = -1.0f;
        }
        __syncthreads();
    }
}

// ---------------- kernel 4: per-batch final top-100 + output assembly ----------------
__global__ void __launch_bounds__(256) k_final(float* __restrict__ out) {
    __shared__ float sc[NCLS * KPOST];   // 9000 floats
    __shared__ float wv[8]; __shared__ int wi[8];
    __shared__ float rv_s;  __shared__ int ri_s;

    int b = blockIdx.x, tid = threadIdx.x;
    const float* src = g_nms_scores + (size_t)b * NCLS * KPOST;
    for (int i = tid; i < NCLS * KPOST; i += 256) sc[i] = src[i];
    __syncthreads();

    int validc = 0;
    for (int p = 0; p < KPOST; ++p) {
        float v = -1e30f; int idx = 0;
        for (int i = tid; i < NCLS * KPOST; i += 256) {
            float sv = sc[i];
            if (sv > v) { v = sv; idx = i; }
        }
        #pragma unroll
        for (int o = 16; o; o >>= 1) {
            float ov = __shfl_down_sync(0xffffffffu, v, o);
            int   oi = __shfl_down_sync(0xffffffffu, idx, o);
            if (ov > v || (ov == v && oi < idx)) { v = ov; idx = oi; }
        }
        if ((tid & 31) == 0) { wv[tid >> 5] = v; wi[tid >> 5] = idx; }
        __syncthreads();
        if (tid < 32) {
            float v2 = (tid < 8) ? wv[tid] : -1e30f;
            int   i2 = (tid < 8) ? wi[tid] : 0;
            #pragma unroll
            for (int o = 4; o; o >>= 1) {
                float ov = __shfl_down_sync(0xffffffffu, v2, o);
                int   oi = __shfl_down_sync(0xffffffffu, i2, o);
                if (ov > v2 || (ov == v2 && oi < i2)) { v2 = ov; i2 = oi; }
            }
            if (tid == 0) { rv_s = v2; ri_s = i2; }
        }
        __syncthreads();
        if (tid == 0) {
            int ri = ri_s; float rv = rv_s;
            float4 bb = g_nms_boxes[(size_t)b * NCLS * KPOST + ri];
            float* ob = out + ((size_t)b * KPOST + p) * 4;
            ob[0] = bb.x; ob[1] = bb.y; ob[2] = bb.z; ob[3] = bb.w;
            out[NBATCH * KPOST * 4 + b * KPOST + p] = rv;
            out[NBATCH * KPOST * 5 + b * KPOST + p] = (float)(ri / KPOST);
            if (rv > 0.0f) validc++;
            sc[ri] = -2.0f;
        }
        __syncthreads();
    }
    if (tid == 0) out[NBATCH * KPOST * 6 + b] = (float)validc;
}

// ---------------- launch ----------------
extern "C" void kernel_launch(void* const* d_in, const int* in_sizes, int n_in,
                              void* d_out, int out_size) {
    const float* a0 = (const float*)d_in[0];
    const float* a1 = (const float*)d_in[1];
    const float4* deltas;
    const float*  logits;
    if (in_sizes[0] == NBATCH * NANCH * 4) { deltas = (const float4*)a0; logits = a1; }
    else                                   { deltas = (const float4*)a1; logits = a0; }
    float* out = (float*)d_out;

    cudaFuncSetAttribute(k_select, cudaFuncAttributeMaxDynamicSharedMemorySize,
                         (NANCH + 2048) * 4);
    cudaFuncSetAttribute(k_nms, cudaFuncAttributeMaxDynamicSharedMemorySize,
                         KPRE * 20);

    dim3 gT((NANCH + 31) / 32, (NCLS + 31) / 32, NBATCH);
    k_transpose<<<gT, dim3(32, 8)>>>(logits);
    k_select<<<NTASK, 512, (NANCH + 2048) * 4>>>(deltas);
    k_nms<<<NTASK, 512, KPRE * 20>>>();
    k_final<<<NBATCH, 256>>>(out);
}

// round 2
// speedup vs baseline: 3.2967x; 3.2967x over previous
#include <cuda_runtime.h>
#include <math.h>

#define NANCH 49104
#define NCLS  90
#define NBATCH 8
#define NTASK (NBATCH * NCLS)   // 720
#define KPRE  5000
#define KPOST 100

// ---------------- scratch (device globals: no allocation allowed) ----------------
__device__ unsigned g_keysT[(size_t)NTASK * NANCH];      // transposed order-preserving keys
__device__ float4   g_cand_boxes[NTASK * KPRE];
__device__ float    g_cand_scores[NTASK * KPRE];
__device__ float4   g_nms_boxes[NTASK * KPOST];
__device__ float    g_nms_scores[NTASK * KPOST];

__constant__ int c_lvl_off[6]    = {0, 36864, 46080, 48384, 48960, 49104};
__constant__ int c_lvl_feat[5]   = {64, 32, 16, 8, 4};
__constant__ int c_lvl_stride[5] = {8, 16, 32, 64, 128};

__device__ __forceinline__ unsigned f2key(float f) {
    unsigned u = __float_as_uint(f);
    return (u & 0x80000000u) ? ~u : (u | 0x80000000u);
}
__device__ __forceinline__ float key2f(unsigned k) {
    unsigned u = (k & 0x80000000u) ? (k ^ 0x80000000u) : ~k;
    return __uint_as_float(u);
}

// ---------------- kernel 1: transpose logits -> keys [B,C,N] ----------------
__global__ void k_transpose(const float* __restrict__ logits) {
    __shared__ unsigned tile[32][33];
    int b  = blockIdx.z;
    int n0 = blockIdx.x * 32, c0 = blockIdx.y * 32;
    #pragma unroll
    for (int j = 0; j < 4; ++j) {
        int ty = threadIdx.y + j * 8;
        int n = n0 + ty, c = c0 + threadIdx.x;
        if (n < NANCH && c < NCLS)
            tile[ty][threadIdx.x] = f2key(logits[((size_t)b * NANCH + n) * NCLS + c]);
    }
    __syncthreads();
    #pragma unroll
    for (int j = 0; j < 4; ++j) {
        int ty = threadIdx.y + j * 8;
        int c = c0 + ty, n = n0 + threadIdx.x;
        if (n < NANCH && c < NCLS)
            g_keysT[((size_t)b * NCLS + c) * NANCH + n] = tile[threadIdx.x][ty];
    }
}

// ---------------- kernel 2: exact top-5000 select (radix) + FP32 decode ----------------
extern __shared__ unsigned smA[];
__global__ void __launch_bounds__(512) k_select(const float4* __restrict__ deltas) {
    unsigned* keys = smA;                       // [NANCH]
    unsigned* hist = smA + NANCH;               // [2048]
    int*      cidx = (int*)(smA + NANCH + 2048);// [KPRE] compacted candidate indices
    __shared__ unsigned partial[512];
    __shared__ int bc_v, bc_k;
    __shared__ int cntG, cntT;
    __shared__ float s_hh[45], s_hw[45];        // anchor half-sizes LUT (level*9 + a)

    int tid  = threadIdx.x;
    int task = blockIdx.x;
    int b    = task / NCLS;

    // anchor LUT: identical FP64 ops as the reference, 45 lanes, ONCE per block
    if (tid < 45) {
        int l = tid / 9, a = tid - l * 9;
        int stride = c_lvl_stride[l];
        int iscale = a / 3, ri = a - iscale * 3;
        double rr   = (ri == 0) ? 1.0 : (ri == 1 ? 0.5 : 2.0);
        double base = exp2((double)iscale / 3.0) * (double)stride * 4.0;
        double sq   = sqrt(rr);
        s_hh[tid] = (float)(base / sq / 2.0);
        s_hw[tid] = (float)(base * sq / 2.0);
    }

    const unsigned* kt = g_keysT + (size_t)task * NANCH;
    for (int i = tid; i < NANCH; i += 512) keys[i] = kt[i];
    __syncthreads();

    unsigned prefix = 0;
    int Krem = KPRE;
    const int SH[3] = {21, 10, 0};
    const int BT[3] = {11, 11, 10};

    for (int pass = 0; pass < 3; ++pass) {
        int shift = SH[pass], bits = BT[pass], nb = 1 << bits;
        for (int i = tid; i < nb; i += 512) hist[i] = 0;
        __syncthreads();
        int top = shift + bits;
        for (int i = tid; i < NANCH; i += 512) {
            unsigned k = keys[i];
            if (pass == 0 || (k >> top) == prefix)
                atomicAdd(&hist[(k >> shift) & (unsigned)(nb - 1)], 1u);
        }
        __syncthreads();
        int cs = nb >> 9;                 // bins per thread (4 or 2)
        int base0 = tid * cs;
        unsigned ssum = 0;
        for (int j2 = 0; j2 < cs; ++j2) ssum += hist[base0 + j2];
        partial[tid] = ssum;
        __syncthreads();
        // inclusive suffix scan (Hillis-Steele)
        for (int off = 1; off < 512; off <<= 1) {
            unsigned add = (tid + off < 512) ? partial[tid + off] : 0u;
            __syncthreads();
            partial[tid] += add;
            __syncthreads();
        }
        unsigned St  = partial[tid];
        unsigned Stn = (tid < 511) ? partial[tid + 1] : 0u;
        if (St >= (unsigned)Krem && Stn < (unsigned)Krem) {
            unsigned acc = Stn;
            for (int j2 = cs - 1; j2 >= 0; --j2) {
                unsigned hv = hist[base0 + j2];
                acc += hv;
                if (acc >= (unsigned)Krem) {
                    bc_v = base0 + j2;
                    bc_k = Krem - (int)(acc - hv);
                    break;
                }
            }
        }
        __syncthreads();
        prefix = (prefix << bits) | (unsigned)bc_v;
        Krem   = bc_k;
        __syncthreads();
    }
    unsigned Tkey = prefix;            // exact 5000th-largest key
    int needT = Krem;                  // ties of Tkey to include

    // ---- compact candidate indices (cheap under divergence) ----
    if (tid == 0) { cntG = 0; cntT = 0; }
    __syncthreads();
    for (int i = tid; i < NANCH; i += 512) {
        unsigned k = keys[i];
        if (k > Tkey) cidx[atomicAdd(&cntG, 1)] = i;
    }
    __syncthreads();
    int G = cntG;
    for (int i = tid; i < NANCH; i += 512) {
        if (keys[i] == Tkey) {
            int t = atomicAdd(&cntT, 1);
            if (t < needT) cidx[G + t] = i;
        }
    }
    __syncthreads();

    // ---- dense FP32 decode: all lanes active ----
    for (int s = tid; s < KPRE; s += 512) {
        int n = cidx[s];
        unsigned key = keys[n];

        int l = 0;
        #pragma unroll
        for (int q = 1; q < 5; ++q) if (n >= c_lvl_off[q]) l = q;
        int j    = n - c_lvl_off[l];
        int cell = j / 9, a = j - cell * 9;
        int feat = c_lvl_feat[l];
        int row  = cell / feat, col = cell - row * feat;
        int stride = c_lvl_stride[l];

        float hh = s_hh[l * 9 + a];
        float hw = s_hw[l * 9 + a];

        float cy = ((float)row + 0.5f) * (float)stride;
        float cx = ((float)col + 0.5f) * (float)stride;
        float ay1 = __fsub_rn(cy, hh), ay2 = __fadd_rn(cy, hh);
        float ax1 = __fsub_rn(cx, hw), ax2 = __fadd_rn(cx, hw);
        float ah  = __fsub_rn(ay2, ay1), aw = __fsub_rn(ax2, ax1);
        float acy = __fmul_rn(__fadd_rn(ay1, ay2), 0.5f);
        float acx = __fmul_rn(__fadd_rn(ax1, ax2), 0.5f);

        float4 d = deltas[(size_t)b * NANCH + n];
        float ncy = __fadd_rn(__fmul_rn(d.x, ah), acy);
        float ncx = __fadd_rn(__fmul_rn(d.y, aw), acx);
        float h   = __fmul_rn(expf(d.z), ah);
        float w   = __fmul_rn(expf(d.w), aw);

        const float inv = 1.0f / 512.0f;
        float y1 = __fsub_rn(ncy, __fmul_rn(h, 0.5f)) * inv;
        float x1 = __fsub_rn(ncx, __fmul_rn(w, 0.5f)) * inv;
        float y2 = __fadd_rn(ncy, __fmul_rn(h, 0.5f)) * inv;
        float x2 = __fadd_rn(ncx, __fmul_rn(w, 0.5f)) * inv;
        y1 = fminf(fmaxf(y1, 0.0f), 1.0f);
        x1 = fminf(fmaxf(x1, 0.0f), 1.0f);
        y2 = fminf(fmaxf(y2, 0.0f), 1.0f);
        x2 = fminf(fmaxf(x2, 0.0f), 1.0f);

        float logit = key2f(key);
        float sc = __fdiv_rn(1.0f, __fadd_rn(1.0f, expf(-logit)));
        g_cand_scores[(size_t)task * KPRE + s] = sc;
        g_cand_boxes [(size_t)task * KPRE + s] = make_float4(y1, x1, y2, x2);
    }
}

// ---------------- kernel 3: greedy NMS (100 picks) per task ----------------
extern __shared__ unsigned char smB[];
__global__ void __launch_bounds__(512) k_nms() {
    float4* bx = (float4*)smB;                 // [KPRE]
    float*  s  = (float*)(smB + KPRE * 16);    // [KPRE]
    __shared__ float wv[16]; __shared__ int wi[16];
    __shared__ float rv_s;   __shared__ int ri_s;

    int tid = threadIdx.x, task = blockIdx.x;
    const float*  cs = g_cand_scores + (size_t)task * KPRE;
    const float4* cb = g_cand_boxes  + (size_t)task * KPRE;
    for (int i = tid; i < KPRE; i += 512) { s[i] = cs[i]; bx[i] = cb[i]; }
    __syncthreads();

    for (int p = 0; p < KPOST; ++p) {
        // ---- stable block argmax ----
        float v = -1e30f; int idx = 0;
        for (int i = tid; i < KPRE; i += 512) {
            float sv = s[i];
            if (sv > v) { v = sv; idx = i; }
        }
        #pragma unroll
        for (int o = 16; o; o >>= 1) {
            float ov = __shfl_down_sync(0xffffffffu, v, o);
            int   oi = __shfl_down_sync(0xffffffffu, idx, o);
            if (ov > v || (ov == v && oi < idx)) { v = ov; idx = oi; }
        }
        if ((tid & 31) == 0) { wv[tid >> 5] = v; wi[tid >> 5] = idx; }
        __syncthreads();
        if (tid < 32) {
            float v2 = (tid < 16) ? wv[tid] : -1e30f;
            int   i2 = (tid < 16) ? wi[tid] : 0;
            #pragma unroll
            for (int o = 8; o; o >>= 1) {
                float ov = __shfl_down_sync(0xffffffffu, v2, o);
                int   oi = __shfl_down_sync(0xffffffffu, i2, o);
                if (ov > v2 || (ov == v2 && oi < i2)) { v2 = ov; i2 = oi; }
            }
            if (tid == 0) { rv_s = v2; ri_s = i2; }
        }
        __syncthreads();
        float rv = rv_s; int ri = ri_s;

        if (rv <= 0.2f) {   // all remaining picks are invalid -> zeros
            for (int q = p + tid; q < KPOST; q += 512) {
                g_nms_scores[(size_t)task * KPOST + q] = 0.0f;
                g_nms_boxes [(size_t)task * KPOST + q] = make_float4(0.f, 0.f, 0.f, 0.f);
            }
            break;
        }
        float4 bb = bx[ri];
        if (tid == 0) {
            g_nms_scores[(size_t)task * KPOST + p] = rv;
            g_nms_boxes [(size_t)task * KPOST + p] = bb;
        }
        // ---- suppression (matches reference: only IoU > 0.5 kills) ----
        float a1 = __fmul_rn(__fsub_rn(bb.z, bb.x), __fsub_rn(bb.w, bb.y));
        for (int i = tid; i < KPRE; i += 512) {
            float4 o4 = bx[i];
            float yy1 = fmaxf(bb.x, o4.x), xx1 = fmaxf(bb.y, o4.y);
            float yy2 = fminf(bb.z, o4.z), xx2 = fminf(bb.w, o4.w);
            float ih = fmaxf(__fsub_rn(yy2, yy1), 0.0f);
            float iw = fmaxf(__fsub_rn(xx2, xx1), 0.0f);
            float inter = __fmul_rn(ih, iw);
            float a2 = __fmul_rn(__fsub_rn(o4.z, o4.x), __fsub_rn(o4.w, o4.y));
            float den = __fadd_rn(__fsub_rn(__fadd_rn(a1, a2), inter), 1e-8f);
            float iou = __fdiv_rn(inter, den);
            if (iou > 0.5f) s[i] = -1.0f;
        }
        __syncthreads();
    }
}

// ---------------- kernel 4: per-batch final top-100 + output assembly ----------------
__global__ void __launch_bounds__(256) k_final(float* __restrict__ out) {
    __shared__ float sc[NCLS * KPOST];   // 9000 floats
    __shared__ float wv[8]; __shared__ int wi[8];
    __shared__ float rv_s;  __shared__ int ri_s;
    __shared__ int   pick[KPOST];
    __shared__ float pval[KPOST];

    int b = blockIdx.x, tid = threadIdx.x;
    const float* src = g_nms_scores + (size_t)b * NCLS * KPOST;
    for (int i = tid; i < NCLS * KPOST; i += 256) sc[i] = src[i];
    __syncthreads();

    for (int p = 0; p < KPOST; ++p) {
        float v = -1e30f; int idx = 0;
        for (int i = tid; i < NCLS * KPOST; i += 256) {
            float sv = sc[i];
            if (sv > v) { v = sv; idx = i; }
        }
        #pragma unroll
        for (int o = 16; o; o >>= 1) {
            float ov = __shfl_down_sync(0xffffffffu, v, o);
            int   oi = __shfl_down_sync(0xffffffffu, idx, o);
            if (ov > v || (ov == v && oi < idx)) { v = ov; idx = oi; }
        }
        if ((tid & 31) == 0) { wv[tid >> 5] = v; wi[tid >> 5] = idx; }
        __syncthreads();
        if (tid < 32) {
            float v2 = (tid < 8) ? wv[tid] : -1e30f;
            int   i2 = (tid < 8) ? wi[tid] : 0;
            #pragma unroll
            for (int o = 4; o; o >>= 1) {
                float ov = __shfl_down_sync(0xffffffffu, v2, o);
                int   oi = __shfl_down_sync(0xffffffffu, i2, o);
                if (ov > v2 || (ov == v2 && oi < i2)) { v2 = ov; i2 = oi; }
            }
            if (tid == 0) {
                pick[p] = i2; pval[p] = v2;
                sc[i2] = -2.0f;       // remove from further picks
            }
        }
        __syncthreads();
    }

    // ---- parallel output assembly ----
    for (int p = tid; p < KPOST; p += 256) {
        int ri = pick[p]; float rv = pval[p];
        float4 bb = g_nms_boxes[(size_t)b * NCLS * KPOST + ri];
        float* ob = out + ((size_t)b * KPOST + p) * 4;
        ob[0] = bb.x; ob[1] = bb.y; ob[2] = bb.z; ob[3] = bb.w;
        out[NBATCH * KPOST * 4 + b * KPOST + p] = rv;
        out[NBATCH * KPOST * 5 + b * KPOST + p] = (float)(ri / KPOST);
    }
    if (tid == 0) {
        int validc = 0;
        for (int p = 0; p < KPOST; ++p) if (pval[p] > 0.0f) validc++;
        out[NBATCH * KPOST * 6 + b] = (float)validc;
    }
}

// ---------------- launch ----------------
extern "C" void kernel_launch(void* const* d_in, const int* in_sizes, int n_in,
                              void* d_out, int out_size) {
    const float* a0 = (const float*)d_in[0];
    const float* a1 = (const float*)d_in[1];
    const float4* deltas;
    const float*  logits;
    if (in_sizes[0] == NBATCH * NANCH * 4) { deltas = (const float4*)a0; logits = a1; }
    else                                   { deltas = (const float4*)a1; logits = a0; }
    float* out = (float*)d_out;

    cudaFuncSetAttribute(k_select, cudaFuncAttributeMaxDynamicSharedMemorySize,
                         (NANCH + 2048 + KPRE) * 4);
    cudaFuncSetAttribute(k_nms, cudaFuncAttributeMaxDynamicSharedMemorySize,
                         KPRE * 20);

    dim3 gT((NANCH + 31) / 32, (NCLS + 31) / 32, NBATCH);
    k_transpose<<<gT, dim3(32, 8)>>>(logits);
    k_select<<<NTASK, 512, (NANCH + 2048 + KPRE) * 4>>>(deltas);
    k_nms<<<NTASK, 512, KPRE * 20>>>();
    k_final<<<NBATCH, 256>>>(out);
}